// round 8
// baseline (speedup 1.0000x reference)
#include <cuda_runtime.h>
#include <cuda_bf16.h>
#include <math.h>
#include <stdint.h>

// FeedForwardExperts, per expert e (E=8):
//   X_e [M=4096, H=1024] @ Wi_e [H, F=4096] -> +bi, exact gelu -> @ Wo_e [F, H] -> +bo
// HMMA (mma.sync bf16) split-precision: x = hi + lo (bf16 each),
// 3 MMAs per K16: Ahi*Bhi + Ahi*Blo + Alo*Bhi, fp32 accumulate.
// R8: 128x64x64 tile, warp tile 32x32, 2-stage cp.async, 2 CTAs/SM
// (R7 was 1 CTA/SM @ tensor=61.5%; second CTA covers the sync bubbles).

namespace {
constexpr int G = 8, E = 8, C = 512, H = 1024, F = 4096;
constexpr int M = G * C;                 // 4096 rows per expert
constexpr int BM = 128, BN = 64, BK = 64;
constexpr int STAGES = 2;
constexpr int LDA_S = 144;               // A smem row stride: 128B data + 16 pad
constexpr int LDB_S = 144;               // B smem row stride: 128B data + 16 pad
constexpr int A_PLANE = BM * LDA_S;      // 18432
constexpr int B_PLANE = BK * LDB_S;      // 9216
constexpr int STAGEB = 2 * A_PLANE + 2 * B_PLANE;   // 55296
constexpr int SMEM_BYTES = STAGES * STAGEB + 256;   // 110848 (~108.3 KB)
}

// ---- device scratch (statics; no allocs allowed) ----
__device__ __nv_bfloat16 g_x_hi [(size_t)G * E * C * H];
__device__ __nv_bfloat16 g_x_lo [(size_t)G * E * C * H];
__device__ __nv_bfloat16 g_wi_hi[(size_t)E * H * F];
__device__ __nv_bfloat16 g_wi_lo[(size_t)E * H * F];
__device__ __nv_bfloat16 g_wo_hi[(size_t)E * F * H];
__device__ __nv_bfloat16 g_wo_lo[(size_t)E * F * H];
__device__ __nv_bfloat16 g_act_hi[(size_t)E * M * F];
__device__ __nv_bfloat16 g_act_lo[(size_t)E * M * F];

// ---------------- helpers ----------------
__device__ __forceinline__ uint32_t smem_u32(const void* p) {
    uint32_t a;
    asm("{ .reg .u64 t; cvta.to.shared.u64 t, %1; cvt.u32.u64 %0, t; }" : "=r"(a) : "l"(p));
    return a;
}
__device__ __forceinline__ void cp_async16(uint32_t dst, const void* src) {
    asm volatile("cp.async.cg.shared.global [%0], [%1], 16;" :: "r"(dst), "l"(src));
}
__device__ __forceinline__ void cp_commit() {
    asm volatile("cp.async.commit_group;");
}
template <int N>
__device__ __forceinline__ void cp_wait() {
    asm volatile("cp.async.wait_group %0;" :: "n"(N));
}
__device__ __forceinline__ void ldsm_x4(uint32_t* r, uint32_t addr) {
    asm volatile("ldmatrix.sync.aligned.m8n8.x4.shared.b16 {%0,%1,%2,%3}, [%4];"
                 : "=r"(r[0]), "=r"(r[1]), "=r"(r[2]), "=r"(r[3]) : "r"(addr));
}
__device__ __forceinline__ void ldsm_x4_t(uint32_t* r, uint32_t addr) {
    asm volatile("ldmatrix.sync.aligned.m8n8.x4.trans.shared.b16 {%0,%1,%2,%3}, [%4];"
                 : "=r"(r[0]), "=r"(r[1]), "=r"(r[2]), "=r"(r[3]) : "r"(addr));
}
__device__ __forceinline__ void mma_bf16(float* d, const uint32_t* a, const uint32_t* b) {
    asm volatile(
        "mma.sync.aligned.m16n8k16.row.col.f32.bf16.bf16.f32 "
        "{%0,%1,%2,%3}, {%4,%5,%6,%7}, {%8,%9}, {%0,%1,%2,%3};"
        : "+f"(d[0]), "+f"(d[1]), "+f"(d[2]), "+f"(d[3])
        : "r"(a[0]), "r"(a[1]), "r"(a[2]), "r"(a[3]), "r"(b[0]), "r"(b[1]));
}
__device__ __forceinline__ uint32_t bfpack(__nv_bfloat16 a, __nv_bfloat16 b) {
    __nv_bfloat162 t; t.x = a; t.y = b;
    return *reinterpret_cast<uint32_t*>(&t);
}
__device__ __forceinline__ float gelu_exact(float x) {
    return 0.5f * x * (1.0f + erff(x * 0.70710678118654752440f));
}

// ---------------- elementwise hi/lo split (prep) ----------------
template <int SEL>
__global__ __launch_bounds__(256)
void split_kernel(const float* __restrict__ src)
{
    __nv_bfloat16* __restrict__ hi = (SEL == 0) ? g_x_hi : (SEL == 1) ? g_wi_hi : g_wo_hi;
    __nv_bfloat16* __restrict__ lo = (SEL == 0) ? g_x_lo : (SEL == 1) ? g_wi_lo : g_wo_lo;
    const size_t i = (size_t)blockIdx.x * 256 + threadIdx.x;   // float4 units
    float4 v = reinterpret_cast<const float4*>(src)[i];
    __nv_bfloat16 hx = __float2bfloat16_rn(v.x);
    __nv_bfloat16 hy = __float2bfloat16_rn(v.y);
    __nv_bfloat16 hz = __float2bfloat16_rn(v.z);
    __nv_bfloat16 hw = __float2bfloat16_rn(v.w);
    uint2 ph = make_uint2(bfpack(hx, hy), bfpack(hz, hw));
    uint2 pl = make_uint2(
        bfpack(__float2bfloat16_rn(v.x - __bfloat162float(hx)),
               __float2bfloat16_rn(v.y - __bfloat162float(hy))),
        bfpack(__float2bfloat16_rn(v.z - __bfloat162float(hz)),
               __float2bfloat16_rn(v.w - __bfloat162float(hw))));
    reinterpret_cast<uint2*>(hi)[i] = ph;
    reinterpret_cast<uint2*>(lo)[i] = pl;
}

// ---------------- HMMA GEMM ----------------
template <bool FIRST>
__global__ __launch_bounds__(256, 2)
void ffn_hmma(const float* __restrict__ bias, float* __restrict__ Out)
{
    constexpr int KD = FIRST ? H : F;
    constexpr int NC = KD / BK;
    constexpr int ldA = FIRST ? H : F;
    constexpr int ldB = FIRST ? F : H;

    extern __shared__ char dsm[];
    const uint32_t sbase = smem_u32(dsm);
    const uint32_t data0 = (sbase + 255) & ~255u;

    const int tid = threadIdx.x, wid = tid >> 5, lane = tid & 31;
    const int e  = blockIdx.z;
    const int m0 = blockIdx.y * BM;
    const int n0 = blockIdx.x * BN;
    const int wm = wid & 3;        // 4 m-groups of 32 rows
    const int wn = wid >> 2;       // 2 n-groups of 32 cols

    const __nv_bfloat16 *Ah, *Al, *Bh, *Bl;
    if (FIRST) {
        const int g = m0 >> 9, cb = m0 & 511;
        const size_t ab = ((size_t)(g * E + e) * C + cb) * H;
        Ah = g_x_hi + ab;  Al = g_x_lo + ab;
        const size_t bb = (size_t)e * H * F + n0;
        Bh = g_wi_hi + bb; Bl = g_wi_lo + bb;
    } else {
        const size_t ab = ((size_t)e * M + m0) * (size_t)F;
        Ah = g_act_hi + ab; Al = g_act_lo + ab;
        const size_t bb = (size_t)e * F * H + n0;
        Bh = g_wo_hi + bb;  Bl = g_wo_lo + bb;
    }

    auto load_chunk = [&](int c, int slot) {
        const uint32_t st  = data0 + slot * STAGEB;
        const uint32_t sAh = st;
        const uint32_t sAl = st + A_PLANE;
        const uint32_t sBh = st + 2 * A_PLANE;
        const uint32_t sBl = st + 2 * A_PLANE + B_PLANE;
        const int k0 = c * BK;
        #pragma unroll
        for (int it = 0; it < 4; ++it) {       // A: 128 rows x 128B = 1024 16B/plane
            const int idx = it * 256 + tid;
            const int row = idx >> 3, c8 = idx & 7;
            const size_t go = (size_t)row * ldA + k0 + c8 * 8;
            const uint32_t so = row * LDA_S + c8 * 16;
            cp_async16(sAh + so, Ah + go);
            cp_async16(sAl + so, Al + go);
        }
        #pragma unroll
        for (int it = 0; it < 2; ++it) {       // B: 64 k-rows x 128B = 512 16B/plane
            const int idx = it * 256 + tid;
            const int row = idx >> 3, c8 = idx & 7;
            const size_t go = (size_t)(k0 + row) * ldB + c8 * 8;
            const uint32_t so = row * LDB_S + c8 * 16;
            cp_async16(sBh + so, Bh + go);
            cp_async16(sBl + so, Bl + go);
        }
    };

    float acc[2][4][4];
    #pragma unroll
    for (int i = 0; i < 2; i++)
        #pragma unroll
        for (int j = 0; j < 4; j++)
            #pragma unroll
            for (int q = 0; q < 4; q++) acc[i][j][q] = 0.0f;

    load_chunk(0, 0);
    cp_commit();

    for (int c = 0; c < NC; ++c) {
        cp_wait<0>();          // chunk c landed (had all of compute(c-1) to fly)
        __syncthreads();       // all warps see it; all done reading slot c&1's old data

        if (c + 1 < NC) { load_chunk(c + 1, (c + 1) & 1); cp_commit(); }

        const uint32_t st = data0 + (c & 1) * STAGEB;
        const uint32_t aBase = st + (wm * 32 + (lane & 15)) * LDA_S + (lane >> 4) * 16;
        const uint32_t bBase = st + 2 * A_PLANE + (lane & 15) * LDB_S
                             + wn * 64 + (lane >> 4) * 16;   // wn*32 cols * 2B

        #pragma unroll
        for (int k16 = 0; k16 < 4; ++k16) {
            uint32_t ah[2][4], al[2][4], bh[2][4], bl[2][4];
            #pragma unroll
            for (int mi = 0; mi < 2; ++mi) {
                const uint32_t a = aBase + mi * 16 * LDA_S + k16 * 32;
                ldsm_x4(ah[mi], a);
                ldsm_x4(al[mi], a + A_PLANE);
            }
            #pragma unroll
            for (int ni = 0; ni < 2; ++ni) {
                const uint32_t b = bBase + k16 * 16 * LDB_S + ni * 32;
                ldsm_x4_t(bh[ni], b);
                ldsm_x4_t(bl[ni], b + B_PLANE);
            }
            #pragma unroll
            for (int mi = 0; mi < 2; ++mi)
                #pragma unroll
                for (int n8 = 0; n8 < 4; ++n8) {
                    const uint32_t* Bhf = &bh[n8 >> 1][(n8 & 1) * 2];
                    const uint32_t* Blf = &bl[n8 >> 1][(n8 & 1) * 2];
                    mma_bf16(acc[mi][n8], ah[mi], Bhf);   // hi*hi
                    mma_bf16(acc[mi][n8], ah[mi], Blf);   // hi*lo
                    mma_bf16(acc[mi][n8], al[mi], Bhf);   // lo*hi
                }
        }
        __syncthreads();       // compute(c) done before iter c+1 reuses slot (c+1)&1? 
                               // slot (c+1)&1 holds chunk c+1 (in flight) — the sync
                               // protects slot c&1 against load(c+2) issued next iter.
    }

    // ---------------- epilogue ----------------
    const int r0 = (lane >> 2);            // 0..7
    const int cl = (lane & 3) * 2;         // 0,2,4,6
    if (FIRST) {
        const float* bv = bias + (size_t)e * F;
        #pragma unroll
        for (int mi = 0; mi < 2; ++mi) {
            const int mbase = m0 + wm * 32 + mi * 16;
            #pragma unroll
            for (int n8 = 0; n8 < 4; ++n8) {
                const int col = n0 + wn * 32 + n8 * 8 + cl;
                const float b0 = bv[col], b1 = bv[col + 1];
                #pragma unroll
                for (int half = 0; half < 2; ++half) {
                    const int m = mbase + r0 + half * 8;
                    const float x0 = acc[mi][n8][half * 2]     + b0;
                    const float x1 = acc[mi][n8][half * 2 + 1] + b1;
                    const float g0 = gelu_exact(x0), g1 = gelu_exact(x1);
                    const __nv_bfloat16 h0 = __float2bfloat16_rn(g0);
                    const __nv_bfloat16 h1 = __float2bfloat16_rn(g1);
                    const size_t off = ((size_t)e * M + m) * (size_t)F + col;
                    *(uint32_t*)&g_act_hi[off] = bfpack(h0, h1);
                    *(uint32_t*)&g_act_lo[off] =
                        bfpack(__float2bfloat16_rn(g0 - __bfloat162float(h0)),
                               __float2bfloat16_rn(g1 - __bfloat162float(h1)));
                }
            }
        }
    } else {
        const float* bv = bias + (size_t)e * H;
        #pragma unroll
        for (int mi = 0; mi < 2; ++mi) {
            const int mbase = m0 + wm * 32 + mi * 16;
            #pragma unroll
            for (int n8 = 0; n8 < 4; ++n8) {
                const int col = n0 + wn * 32 + n8 * 8 + cl;
                const float b0 = bv[col], b1 = bv[col + 1];
                #pragma unroll
                for (int half = 0; half < 2; ++half) {
                    const int m = mbase + r0 + half * 8;
                    const int g = m >> 9, cc = m & 511;
                    float2 o;
                    o.x = acc[mi][n8][half * 2]     + b0;
                    o.y = acc[mi][n8][half * 2 + 1] + b1;
                    *(float2*)&Out[((size_t)(g * E + e) * C + cc) * (size_t)H + col] = o;
                }
            }
        }
    }
}

extern "C" void kernel_launch(void* const* d_in, const int* in_sizes, int n_in,
                              void* d_out, int out_size)
{
    const float* inputs = (const float*)d_in[0];
    const float* wi     = (const float*)d_in[1];
    const float* bi     = (const float*)d_in[2];
    const float* wo     = (const float*)d_in[3];
    const float* bo     = (const float*)d_in[4];
    float* out          = (float*)d_out;

    cudaFuncSetAttribute(ffn_hmma<true>,  cudaFuncAttributeMaxDynamicSharedMemorySize, SMEM_BYTES);
    cudaFuncSetAttribute(ffn_hmma<false>, cudaFuncAttributeMaxDynamicSharedMemorySize, SMEM_BYTES);

    split_kernel<0><<<(G * E * C * (H / 4)) / 256, 256>>>(inputs);
    split_kernel<1><<<(E * H * (F / 4)) / 256, 256>>>(wi);
    split_kernel<2><<<(E * F * (H / 4)) / 256, 256>>>(wo);

    ffn_hmma<true ><<<dim3(F / BN, M / BM, E), 256, SMEM_BYTES>>>(bi, nullptr);
    ffn_hmma<false><<<dim3(H / BN, M / BM, E), 256, SMEM_BYTES>>>(bo, out);
}

// round 14
// speedup vs baseline: 1.5082x; 1.5082x over previous
#include <cuda_runtime.h>
#include <cuda_fp16.h>
#include <math.h>
#include <stdint.h>

// FeedForwardExperts, per expert e (E=8):
//   X_e [M=4096, H=1024] @ Wi_e [H, F=1024x4096] -> +bi, exact gelu -> @ Wo_e [F, H] -> +bo
// fp16 HMMA, 2 MMAs per K16. Weights split hi+lo fp16 (residual ~2^-22),
// activations/inputs single fp16 (~2.8e-4 rms rounding per stage).
// A: single smem plane; B: hi+lo planes. 128x128x32 tile, 8 warps, 32x64 warp
// tile, 3-stage cp.async, 1 CTA/SM (R8 falsified the occupancy hypothesis;
// the mma.sync instruction count is the binding constraint).
// R11: third submission of this compute path (R9/R10 died at the infra level
// with no compile or run output; R6->R7 established identical-resubmit
// recovery). Kernels renamed as a hedge; compute path unchanged.

namespace {
constexpr int G = 8, E = 8, C = 512, H = 1024, F = 4096;
constexpr int M = G * C;                 // 4096 rows per expert
constexpr int BM = 128, BN = 128, BK = 32;
constexpr int STAGES = 3;
constexpr int LDA_S = 80;                // A smem row stride (64B data + 16 pad)
constexpr int LDB_S = 272;               // B smem row stride (256B data + 16 pad)
constexpr int A_PLANE = BM * LDA_S;      // 10240
constexpr int B_PLANE = BK * LDB_S;      // 8704
constexpr int STAGEB = A_PLANE + 2 * B_PLANE;      // 27648
constexpr int SMEM_BYTES = STAGES * STAGEB + 256;  // 83200 (~81.3 KB)
}

// ---- device scratch (statics; no allocs allowed) ----
__device__ __half s_x    [(size_t)G * E * C * H];   // inputs, fp16
__device__ __half s_wi_hi[(size_t)E * H * F];
__device__ __half s_wi_lo[(size_t)E * H * F];
__device__ __half s_wo_hi[(size_t)E * F * H];
__device__ __half s_wo_lo[(size_t)E * F * H];
__device__ __half s_act  [(size_t)E * M * F];       // gelu output, fp16

// ---------------- helpers ----------------
__device__ __forceinline__ uint32_t smem_u32(const void* p) {
    uint32_t a;
    asm("{ .reg .u64 t; cvta.to.shared.u64 t, %1; cvt.u32.u64 %0, t; }" : "=r"(a) : "l"(p));
    return a;
}
__device__ __forceinline__ void cp_async16(uint32_t dst, const void* src) {
    asm volatile("cp.async.cg.shared.global [%0], [%1], 16;" :: "r"(dst), "l"(src));
}
__device__ __forceinline__ void cp_commit() {
    asm volatile("cp.async.commit_group;");
}
template <int N>
__device__ __forceinline__ void cp_wait() {
    asm volatile("cp.async.wait_group %0;" :: "n"(N));
}
__device__ __forceinline__ void ldsm_x4(uint32_t* r, uint32_t addr) {
    asm volatile("ldmatrix.sync.aligned.m8n8.x4.shared.b16 {%0,%1,%2,%3}, [%4];"
                 : "=r"(r[0]), "=r"(r[1]), "=r"(r[2]), "=r"(r[3]) : "r"(addr));
}
__device__ __forceinline__ void ldsm_x4_t(uint32_t* r, uint32_t addr) {
    asm volatile("ldmatrix.sync.aligned.m8n8.x4.trans.shared.b16 {%0,%1,%2,%3}, [%4];"
                 : "=r"(r[0]), "=r"(r[1]), "=r"(r[2]), "=r"(r[3]) : "r"(addr));
}
__device__ __forceinline__ void mma_f16(float* d, const uint32_t* a, const uint32_t* b) {
    asm volatile(
        "mma.sync.aligned.m16n8k16.row.col.f32.f16.f16.f32 "
        "{%0,%1,%2,%3}, {%4,%5,%6,%7}, {%8,%9}, {%0,%1,%2,%3};"
        : "+f"(d[0]), "+f"(d[1]), "+f"(d[2]), "+f"(d[3])
        : "r"(a[0]), "r"(a[1]), "r"(a[2]), "r"(a[3]), "r"(b[0]), "r"(b[1]));
}
__device__ __forceinline__ uint32_t hpack(__half a, __half b) {
    __half2 t; t.x = a; t.y = b;
    return *reinterpret_cast<uint32_t*>(&t);
}
__device__ __forceinline__ float gelu_exact(float x) {
    return 0.5f * x * (1.0f + erff(x * 0.70710678118654752440f));
}

// ---------------- prep kernels ----------------
// inputs fp32 -> fp16 single plane
__global__ __launch_bounds__(256)
void ffx_conv_input(const float* __restrict__ src)
{
    const size_t i = (size_t)blockIdx.x * 256 + threadIdx.x;   // float4 units
    float4 v = reinterpret_cast<const float4*>(src)[i];
    uint2 p = make_uint2(hpack(__float2half_rn(v.x), __float2half_rn(v.y)),
                         hpack(__float2half_rn(v.z), __float2half_rn(v.w)));
    reinterpret_cast<uint2*>(s_x)[i] = p;
}

// weights fp32 -> fp16 hi + lo planes. SEL: 0 = wi, 1 = wo
template <int SEL>
__global__ __launch_bounds__(256)
void ffx_split_weight(const float* __restrict__ src)
{
    __half* __restrict__ hi = (SEL == 0) ? s_wi_hi : s_wo_hi;
    __half* __restrict__ lo = (SEL == 0) ? s_wi_lo : s_wo_lo;
    const size_t i = (size_t)blockIdx.x * 256 + threadIdx.x;   // float4 units
    float4 v = reinterpret_cast<const float4*>(src)[i];
    __half hx = __float2half_rn(v.x);
    __half hy = __float2half_rn(v.y);
    __half hz = __float2half_rn(v.z);
    __half hw = __float2half_rn(v.w);
    uint2 ph = make_uint2(hpack(hx, hy), hpack(hz, hw));
    uint2 pl = make_uint2(
        hpack(__float2half_rn(v.x - __half2float(hx)),
              __float2half_rn(v.y - __half2float(hy))),
        hpack(__float2half_rn(v.z - __half2float(hz)),
              __float2half_rn(v.w - __half2float(hw))));
    reinterpret_cast<uint2*>(hi)[i] = ph;
    reinterpret_cast<uint2*>(lo)[i] = pl;
}

// ---------------- HMMA GEMM ----------------
template <bool FIRST>
__global__ __launch_bounds__(256, 1)
void ffx_gemm(const float* __restrict__ bias, float* __restrict__ Out)
{
    constexpr int KD = FIRST ? H : F;          // reduction dim
    constexpr int NC = KD / BK;                // k-chunks
    constexpr int ldA = FIRST ? H : F;         // elems
    constexpr int ldB = FIRST ? F : H;

    extern __shared__ char dsm[];
    const uint32_t sbase = smem_u32(dsm);
    const uint32_t data0 = (sbase + 255) & ~255u;

    const int tid = threadIdx.x, wid = tid >> 5, lane = tid & 31;
    const int e  = blockIdx.z;
    const int m0 = blockIdx.y * BM;
    const int n0 = blockIdx.x * BN;
    const int wm = wid & 3;        // 4 m-groups of 32 rows
    const int wn = wid >> 2;       // 2 n-groups of 64 cols

    const __half *Ap, *Bh, *Bl;
    if (FIRST) {
        const int g = m0 >> 9, cb = m0 & 511;
        Ap = s_x + ((size_t)(g * E + e) * C + cb) * H;
        const size_t bb = (size_t)e * H * F + n0;
        Bh = s_wi_hi + bb; Bl = s_wi_lo + bb;
    } else {
        Ap = s_act + ((size_t)e * M + m0) * (size_t)F;
        const size_t bb = (size_t)e * F * H + n0;
        Bh = s_wo_hi + bb; Bl = s_wo_lo + bb;
    }

    auto load_chunk = [&](int c, int slot) {
        const uint32_t st  = data0 + slot * STAGEB;
        const uint32_t sA  = st;
        const uint32_t sBh = st + A_PLANE;
        const uint32_t sBl = st + A_PLANE + B_PLANE;
        const int k0 = c * BK;
        #pragma unroll
        for (int it = 0; it < 2; ++it) {           // A: 128 rows x 64B = 512 chunks
            const int idx = it * 256 + tid;
            const int row = idx >> 2, c4 = idx & 3;
            const size_t go = (size_t)row * ldA + k0 + c4 * 8;
            cp_async16(sA + row * LDA_S + c4 * 16, Ap + go);
        }
        #pragma unroll
        for (int it = 0; it < 2; ++it) {           // B: 32 rows x 256B = 512/plane
            const int idx = it * 256 + tid;
            const int row = idx >> 4, c16 = idx & 15;
            const size_t go = (size_t)(k0 + row) * ldB + c16 * 8;
            const uint32_t so = row * LDB_S + c16 * 16;
            cp_async16(sBh + so, Bh + go);
            cp_async16(sBl + so, Bl + go);
        }
    };

    float acc[2][8][4];
    #pragma unroll
    for (int i = 0; i < 2; i++)
        #pragma unroll
        for (int j = 0; j < 8; j++)
            #pragma unroll
            for (int q = 0; q < 4; q++) acc[i][j][q] = 0.0f;

    #pragma unroll
    for (int s = 0; s < STAGES - 1; ++s) { load_chunk(s, s); cp_commit(); }

    for (int c = 0; c < NC; ++c) {
        cp_wait<STAGES - 2>();
        __syncthreads();

        const int slot = c % STAGES;
        const uint32_t st = data0 + slot * STAGEB;
        const uint32_t aBase = st + (wm * 32 + (lane & 15)) * LDA_S + (lane >> 4) * 16;
        const uint32_t bBase = st + A_PLANE + (lane & 15) * LDB_S
                             + wn * 128 + (lane >> 4) * 16;   // wn*64 cols * 2B

        #pragma unroll
        for (int k16 = 0; k16 < 2; ++k16) {
            uint32_t ah[2][4], bh[4][4], bl[4][4];
            #pragma unroll
            for (int mi = 0; mi < 2; ++mi)
                ldsm_x4(ah[mi], aBase + mi * 16 * LDA_S + k16 * 32);
            #pragma unroll
            for (int ni = 0; ni < 4; ++ni) {
                const uint32_t b = bBase + k16 * 16 * LDB_S + ni * 32;
                ldsm_x4_t(bh[ni], b);
                ldsm_x4_t(bl[ni], b + B_PLANE);
            }
            #pragma unroll
            for (int mi = 0; mi < 2; ++mi)
                #pragma unroll
                for (int n8 = 0; n8 < 8; ++n8) {
                    mma_f16(acc[mi][n8], ah[mi], &bh[n8 >> 1][(n8 & 1) * 2]);  // A*Bhi
                    mma_f16(acc[mi][n8], ah[mi], &bl[n8 >> 1][(n8 & 1) * 2]);  // A*Blo
                }
        }

        if (c + STAGES - 1 < NC) load_chunk(c + STAGES - 1, (c + STAGES - 1) % STAGES);
        cp_commit();
    }

    // ---------------- epilogue ----------------
    const int r0 = (lane >> 2);            // 0..7
    const int cl = (lane & 3) * 2;         // 0,2,4,6
    if (FIRST) {
        const float* bv = bias + (size_t)e * F;
        #pragma unroll
        for (int mi = 0; mi < 2; ++mi) {
            const int mbase = m0 + wm * 32 + mi * 16;
            #pragma unroll
            for (int n8 = 0; n8 < 8; ++n8) {
                const int col = n0 + wn * 64 + n8 * 8 + cl;
                const float b0 = bv[col], b1 = bv[col + 1];
                #pragma unroll
                for (int half = 0; half < 2; ++half) {
                    const int m = mbase + r0 + half * 8;
                    const float x0 = acc[mi][n8][half * 2]     + b0;
                    const float x1 = acc[mi][n8][half * 2 + 1] + b1;
                    const size_t off = ((size_t)e * M + m) * (size_t)F + col;
                    *(uint32_t*)&s_act[off] =
                        hpack(__float2half_rn(gelu_exact(x0)),
                              __float2half_rn(gelu_exact(x1)));
                }
            }
        }
    } else {
        const float* bv = bias + (size_t)e * H;
        #pragma unroll
        for (int mi = 0; mi < 2; ++mi) {
            const int mbase = m0 + wm * 32 + mi * 16;
            #pragma unroll
            for (int n8 = 0; n8 < 8; ++n8) {
                const int col = n0 + wn * 64 + n8 * 8 + cl;
                const float b0 = bv[col], b1 = bv[col + 1];
                #pragma unroll
                for (int half = 0; half < 2; ++half) {
                    const int m = mbase + r0 + half * 8;
                    const int g = m >> 9, cc = m & 511;
                    float2 o;
                    o.x = acc[mi][n8][half * 2]     + b0;
                    o.y = acc[mi][n8][half * 2 + 1] + b1;
                    *(float2*)&Out[((size_t)(g * E + e) * C + cc) * (size_t)H + col] = o;
                }
            }
        }
    }
}

extern "C" void kernel_launch(void* const* d_in, const int* in_sizes, int n_in,
                              void* d_out, int out_size)
{
    const float* inputs = (const float*)d_in[0];
    const float* wi     = (const float*)d_in[1];
    const float* bi     = (const float*)d_in[2];
    const float* wo     = (const float*)d_in[3];
    const float* bo     = (const float*)d_in[4];
    float* out          = (float*)d_out;

    cudaFuncSetAttribute(ffx_gemm<true>,  cudaFuncAttributeMaxDynamicSharedMemorySize, SMEM_BYTES);
    cudaFuncSetAttribute(ffx_gemm<false>, cudaFuncAttributeMaxDynamicSharedMemorySize, SMEM_BYTES);

    ffx_conv_input    <<<(G * E * C * (H / 4)) / 256, 256>>>(inputs);
    ffx_split_weight<0><<<(E * H * (F / 4)) / 256, 256>>>(wi);
    ffx_split_weight<1><<<(E * F * (H / 4)) / 256, 256>>>(wo);

    ffx_gemm<true ><<<dim3(F / BN, M / BM, E), 256, SMEM_BYTES>>>(bi, nullptr);
    ffx_gemm<false><<<dim3(H / BN, M / BM, E), 256, SMEM_BYTES>>>(bo, out);
}

// round 17
// speedup vs baseline: 2.1272x; 1.4105x over previous
#include <cuda_runtime.h>
#include <cuda_fp16.h>
#include <math.h>
#include <stdint.h>

// FeedForwardExperts, per expert e (E=8):
//   X_e [M=4096, H=1024] @ Wi_e [H, F=4096] -> +bi, exact gelu -> @ Wo_e [F, H] -> +bo
// R15: single fp16 everywhere, 1 MMA per K16 (R14 proved dur scales with MMA
// count at a fixed ~60% tensor-pipe plateau; fp16 4-source rounding budget
// ~5e-4 rms stays under the 1e-3 gate with 2x margin).
// Geometry: 128x128x32 tile, 8 warps, 32x64 warp tile, 3-stage cp.async,
// 1 CTA/SM (twice-proven shape).

namespace {
constexpr int G = 8, E = 8, C = 512, H = 1024, F = 4096;
constexpr int M = G * C;                 // 4096 rows per expert
constexpr int BM = 128, BN = 128, BK = 32;
constexpr int STAGES = 3;
constexpr int LDA_S = 80;                // A smem row stride (64B data + 16 pad)
constexpr int LDB_S = 272;               // B smem row stride (256B data + 16 pad)
constexpr int A_PLANE = BM * LDA_S;      // 10240
constexpr int B_PLANE = BK * LDB_S;      // 8704
constexpr int STAGEB = A_PLANE + B_PLANE;          // 18944
constexpr int SMEM_BYTES = STAGES * STAGEB + 256;  // 57088 (~55.8 KB)
}

// ---- device scratch (statics; no allocs allowed) ----
__device__ __half s_x  [(size_t)G * E * C * H];   // inputs, fp16
__device__ __half s_wi [(size_t)E * H * F];
__device__ __half s_wo [(size_t)E * F * H];
__device__ __half s_act[(size_t)E * M * F];       // gelu output, fp16

// ---------------- helpers ----------------
__device__ __forceinline__ uint32_t smem_u32(const void* p) {
    uint32_t a;
    asm("{ .reg .u64 t; cvta.to.shared.u64 t, %1; cvt.u32.u64 %0, t; }" : "=r"(a) : "l"(p));
    return a;
}
__device__ __forceinline__ void cp_async16(uint32_t dst, const void* src) {
    asm volatile("cp.async.cg.shared.global [%0], [%1], 16;" :: "r"(dst), "l"(src));
}
__device__ __forceinline__ void cp_commit() {
    asm volatile("cp.async.commit_group;");
}
template <int N>
__device__ __forceinline__ void cp_wait() {
    asm volatile("cp.async.wait_group %0;" :: "n"(N));
}
__device__ __forceinline__ void ldsm_x4(uint32_t* r, uint32_t addr) {
    asm volatile("ldmatrix.sync.aligned.m8n8.x4.shared.b16 {%0,%1,%2,%3}, [%4];"
                 : "=r"(r[0]), "=r"(r[1]), "=r"(r[2]), "=r"(r[3]) : "r"(addr));
}
__device__ __forceinline__ void ldsm_x4_t(uint32_t* r, uint32_t addr) {
    asm volatile("ldmatrix.sync.aligned.m8n8.x4.trans.shared.b16 {%0,%1,%2,%3}, [%4];"
                 : "=r"(r[0]), "=r"(r[1]), "=r"(r[2]), "=r"(r[3]) : "r"(addr));
}
__device__ __forceinline__ void mma_f16(float* d, const uint32_t* a, const uint32_t* b) {
    asm volatile(
        "mma.sync.aligned.m16n8k16.row.col.f32.f16.f16.f32 "
        "{%0,%1,%2,%3}, {%4,%5,%6,%7}, {%8,%9}, {%0,%1,%2,%3};"
        : "+f"(d[0]), "+f"(d[1]), "+f"(d[2]), "+f"(d[3])
        : "r"(a[0]), "r"(a[1]), "r"(a[2]), "r"(a[3]), "r"(b[0]), "r"(b[1]));
}
__device__ __forceinline__ uint32_t hpack(__half a, __half b) {
    __half2 t; t.x = a; t.y = b;
    return *reinterpret_cast<uint32_t*>(&t);
}
__device__ __forceinline__ float gelu_exact(float x) {
    return 0.5f * x * (1.0f + erff(x * 0.70710678118654752440f));
}

// ---------------- prep: fp32 -> fp16 convert ----------------
// SEL: 0 = inputs -> s_x, 1 = wi -> s_wi, 2 = wo -> s_wo
template <int SEL>
__global__ __launch_bounds__(256)
void ffx_convert(const float* __restrict__ src)
{
    __half* __restrict__ dst = (SEL == 0) ? s_x : (SEL == 1) ? s_wi : s_wo;
    const size_t i = (size_t)blockIdx.x * 256 + threadIdx.x;   // float4 units
    float4 v = reinterpret_cast<const float4*>(src)[i];
    uint2 p = make_uint2(hpack(__float2half_rn(v.x), __float2half_rn(v.y)),
                         hpack(__float2half_rn(v.z), __float2half_rn(v.w)));
    reinterpret_cast<uint2*>(dst)[i] = p;
}

// ---------------- HMMA GEMM ----------------
template <bool FIRST>
__global__ __launch_bounds__(256, 1)
void ffx_gemm(const float* __restrict__ bias, float* __restrict__ Out)
{
    constexpr int KD = FIRST ? H : F;          // reduction dim
    constexpr int NC = KD / BK;                // k-chunks
    constexpr int ldA = FIRST ? H : F;         // elems
    constexpr int ldB = FIRST ? F : H;

    extern __shared__ char dsm[];
    const uint32_t sbase = smem_u32(dsm);
    const uint32_t data0 = (sbase + 255) & ~255u;

    const int tid = threadIdx.x, wid = tid >> 5, lane = tid & 31;
    const int e  = blockIdx.z;
    const int m0 = blockIdx.y * BM;
    const int n0 = blockIdx.x * BN;
    const int wm = wid & 3;        // 4 m-groups of 32 rows
    const int wn = wid >> 2;       // 2 n-groups of 64 cols

    const __half *Ap, *Bp;
    if (FIRST) {
        const int g = m0 >> 9, cb = m0 & 511;
        Ap = s_x + ((size_t)(g * E + e) * C + cb) * H;
        Bp = s_wi + (size_t)e * H * F + n0;
    } else {
        Ap = s_act + ((size_t)e * M + m0) * (size_t)F;
        Bp = s_wo + (size_t)e * F * H + n0;
    }

    auto load_chunk = [&](int c, int slot) {
        const uint32_t st = data0 + slot * STAGEB;
        const uint32_t sA = st;
        const uint32_t sB = st + A_PLANE;
        const int k0 = c * BK;
        #pragma unroll
        for (int it = 0; it < 2; ++it) {           // A: 128 rows x 64B = 512 chunks
            const int idx = it * 256 + tid;
            const int row = idx >> 2, c4 = idx & 3;
            const size_t go = (size_t)row * ldA + k0 + c4 * 8;
            cp_async16(sA + row * LDA_S + c4 * 16, Ap + go);
        }
        #pragma unroll
        for (int it = 0; it < 2; ++it) {           // B: 32 rows x 256B = 512 chunks
            const int idx = it * 256 + tid;
            const int row = idx >> 4, c16 = idx & 15;
            const size_t go = (size_t)(k0 + row) * ldB + c16 * 8;
            cp_async16(sB + row * LDB_S + c16 * 16, Bp + go);
        }
    };

    float acc[2][8][4];
    #pragma unroll
    for (int i = 0; i < 2; i++)
        #pragma unroll
        for (int j = 0; j < 8; j++)
            #pragma unroll
            for (int q = 0; q < 4; q++) acc[i][j][q] = 0.0f;

    #pragma unroll
    for (int s = 0; s < STAGES - 1; ++s) { load_chunk(s, s); cp_commit(); }

    for (int c = 0; c < NC; ++c) {
        cp_wait<STAGES - 2>();
        __syncthreads();

        const int slot = c % STAGES;
        const uint32_t st = data0 + slot * STAGEB;
        const uint32_t aBase = st + (wm * 32 + (lane & 15)) * LDA_S + (lane >> 4) * 16;
        const uint32_t bBase = st + A_PLANE + (lane & 15) * LDB_S
                             + wn * 128 + (lane >> 4) * 16;   // wn*64 cols * 2B

        #pragma unroll
        for (int k16 = 0; k16 < 2; ++k16) {
            uint32_t ah[2][4], bh[4][4];
            #pragma unroll
            for (int mi = 0; mi < 2; ++mi)
                ldsm_x4(ah[mi], aBase + mi * 16 * LDA_S + k16 * 32);
            #pragma unroll
            for (int ni = 0; ni < 4; ++ni)
                ldsm_x4_t(bh[ni], bBase + k16 * 16 * LDB_S + ni * 32);
            #pragma unroll
            for (int mi = 0; mi < 2; ++mi)
                #pragma unroll
                for (int n8 = 0; n8 < 8; ++n8)
                    mma_f16(acc[mi][n8], ah[mi], &bh[n8 >> 1][(n8 & 1) * 2]);
        }

        if (c + STAGES - 1 < NC) load_chunk(c + STAGES - 1, (c + STAGES - 1) % STAGES);
        cp_commit();
    }

    // ---------------- epilogue ----------------
    const int r0 = (lane >> 2);            // 0..7
    const int cl = (lane & 3) * 2;         // 0,2,4,6
    if (FIRST) {
        const float* bv = bias + (size_t)e * F;
        #pragma unroll
        for (int mi = 0; mi < 2; ++mi) {
            const int mbase = m0 + wm * 32 + mi * 16;
            #pragma unroll
            for (int n8 = 0; n8 < 8; ++n8) {
                const int col = n0 + wn * 64 + n8 * 8 + cl;
                const float b0 = bv[col], b1 = bv[col + 1];
                #pragma unroll
                for (int half = 0; half < 2; ++half) {
                    const int m = mbase + r0 + half * 8;
                    const float x0 = acc[mi][n8][half * 2]     + b0;
                    const float x1 = acc[mi][n8][half * 2 + 1] + b1;
                    const size_t off = ((size_t)e * M + m) * (size_t)F + col;
                    *(uint32_t*)&s_act[off] =
                        hpack(__float2half_rn(gelu_exact(x0)),
                              __float2half_rn(gelu_exact(x1)));
                }
            }
        }
    } else {
        const float* bv = bias + (size_t)e * H;
        #pragma unroll
        for (int mi = 0; mi < 2; ++mi) {
            const int mbase = m0 + wm * 32 + mi * 16;
            #pragma unroll
            for (int n8 = 0; n8 < 8; ++n8) {
                const int col = n0 + wn * 64 + n8 * 8 + cl;
                const float b0 = bv[col], b1 = bv[col + 1];
                #pragma unroll
                for (int half = 0; half < 2; ++half) {
                    const int m = mbase + r0 + half * 8;
                    const int g = m >> 9, cc = m & 511;
                    float2 o;
                    o.x = acc[mi][n8][half * 2]     + b0;
                    o.y = acc[mi][n8][half * 2 + 1] + b1;
                    *(float2*)&Out[((size_t)(g * E + e) * C + cc) * (size_t)H + col] = o;
                }
            }
        }
    }
}

extern "C" void kernel_launch(void* const* d_in, const int* in_sizes, int n_in,
                              void* d_out, int out_size)
{
    const float* inputs = (const float*)d_in[0];
    const float* wi     = (const float*)d_in[1];
    const float* bi     = (const float*)d_in[2];
    const float* wo     = (const float*)d_in[3];
    const float* bo     = (const float*)d_in[4];
    float* out          = (float*)d_out;

    cudaFuncSetAttribute(ffx_gemm<true>,  cudaFuncAttributeMaxDynamicSharedMemorySize, SMEM_BYTES);
    cudaFuncSetAttribute(ffx_gemm<false>, cudaFuncAttributeMaxDynamicSharedMemorySize, SMEM_BYTES);

    ffx_convert<0><<<(G * E * C * (H / 4)) / 256, 256>>>(inputs);
    ffx_convert<1><<<(E * H * (F / 4)) / 256, 256>>>(wi);
    ffx_convert<2><<<(E * F * (H / 4)) / 256, 256>>>(wo);

    ffx_gemm<true ><<<dim3(F / BN, M / BM, E), 256, SMEM_BYTES>>>(bi, nullptr);
    ffx_gemm<false><<<dim3(H / BN, M / BM, E), 256, SMEM_BYTES>>>(bo, out);
}